// round 6
// baseline (speedup 1.0000x reference)
#include <cuda_runtime.h>

// Problem constants
#define TQ     8192      // T/2 output positions
#define DM     768       // model dim
#define NBINS  1024      // codebook entries
#define TIN    16384     // input T
#define KCONV  1536      // conv GEMM K = D*2

// Scratch (allocation-free rule: __device__ globals)
__device__ float g_X[TQ * DM];          // conv output, [t'][d] row-major (25 MB)
__device__ float g_cnorm[NBINS];        // ||c_k||^2
__device__ float g_pmin[TQ * 8];        // per-(row, n-tile) partial min
__device__ int   g_pidx[TQ * 8];        // per-(row, n-tile) partial argmin

// ---------------------------------------------------------------------------
// Kernel 0: codebook squared norms. One warp per codebook row.
// ---------------------------------------------------------------------------
__global__ void cnorm_kernel(const float* __restrict__ cb) {
    int warp = (blockIdx.x * blockDim.x + threadIdx.x) >> 5;
    int lane = threadIdx.x & 31;
    if (warp >= NBINS) return;
    const float* row = cb + warp * DM;
    float s = 0.f;
    for (int i = lane; i < DM; i += 32) { float v = row[i]; s += v * v; }
    #pragma unroll
    for (int o = 16; o; o >>= 1) s += __shfl_xor_sync(0xffffffffu, s, o);
    if (lane == 0) g_cnorm[warp] = s;
}

// ---------------------------------------------------------------------------
// Kernel 1: conv-as-GEMM.  X[t', d_out] = sum_dk A[t',dk] * W[d_out,dk] + b
//   A[t', 2*d_in+k] = ssl[d_in*TIN + 2*t' + k]   (batch 0 only)
//   W row-major [768][1536]  (conv_w [O][I][K] flattened, cross-correlation)
// BM=BN=128, BK=16, 256 threads, 8x8 microtile.
// ---------------------------------------------------------------------------
__global__ __launch_bounds__(256) void conv_gemm_kernel(
    const float* __restrict__ ssl,     // batch 0 base: [768][16384]
    const float* __restrict__ W,       // [768][1536]
    const float* __restrict__ bias)    // [768]
{
    __shared__ float As[16][128 + 4];  // [dk_local][m_local]
    __shared__ float Bs[16][128 + 4];  // [dk_local][n_local]

    const int tid = threadIdx.x;
    const int m0  = blockIdx.x * 128;  // t' base
    const int n0  = blockIdx.y * 128;  // d_out base
    const int tx  = tid & 15;
    const int ty  = tid >> 4;
    const int r   = tid & 127;         // A-load row (t' local)
    const int di0 = tid >> 7;          // A-load d_in phase (0..1)

    float acc[8][8];
    #pragma unroll
    for (int i = 0; i < 8; ++i)
        #pragma unroll
        for (int j = 0; j < 8; ++j) acc[i][j] = 0.f;

    for (int kb = 0; kb < KCONV / 16; ++kb) {
        // A tile: 8 d_in rows x 128 t' as contiguous float2 (both conv taps)
        #pragma unroll
        for (int l = 0; l < 4; ++l) {
            int di = di0 + l * 2;                           // 0..7
            const float2 v = *(const float2*)(
                ssl + (size_t)(kb * 8 + di) * TIN + 2 * (m0 + r));
            As[2 * di + 0][r] = v.x;                        // k = 0 tap
            As[2 * di + 1][r] = v.y;                        // k = 1 tap
        }
        // B tile: W[n0+row][kb*16 .. +16), stored transposed into Bs[dk][n]
        #pragma unroll
        for (int it = 0; it < 2; ++it) {
            int idx = tid + it * 256;
            int row = idx >> 2;
            int c4  = (idx & 3) * 4;
            const float4 w4 = *(const float4*)(
                W + (size_t)(n0 + row) * KCONV + kb * 16 + c4);
            Bs[c4 + 0][row] = w4.x;  Bs[c4 + 1][row] = w4.y;
            Bs[c4 + 2][row] = w4.z;  Bs[c4 + 3][row] = w4.w;
        }
        __syncthreads();

        #pragma unroll
        for (int kk = 0; kk < 16; ++kk) {
            float a[8], b[8];
            #pragma unroll
            for (int i = 0; i < 8; ++i) a[i] = As[kk][ty * 8 + i];
            #pragma unroll
            for (int j = 0; j < 8; ++j) b[j] = Bs[kk][tx * 8 + j];
            #pragma unroll
            for (int i = 0; i < 8; ++i)
                #pragma unroll
                for (int j = 0; j < 8; ++j) acc[i][j] += a[i] * b[j];
        }
        __syncthreads();
    }

    // Epilogue: add bias, store [t'][d] row-major
    #pragma unroll
    for (int i = 0; i < 8; ++i) {
        int m = m0 + ty * 8 + i;
        #pragma unroll
        for (int j = 0; j < 8; ++j) {
            int n = n0 + tx * 8 + j;
            g_X[(size_t)m * DM + n] = acc[i][j] + __ldg(&bias[n]);
        }
    }
}

// ---------------------------------------------------------------------------
// Kernel 2: distance GEMM + per-tile argmin.
//   dot[t', n] = sum_k X[t',k] * cb[n,k];  d2 = cnorm[n] - 2*dot  (|x|^2 drops)
//   Each block: 128 rows x 128 bins, writes (min, argmin) partial per row.
// ---------------------------------------------------------------------------
__global__ __launch_bounds__(256) void dist_kernel(const float* __restrict__ cb)
{
    __shared__ float As[16][128 + 4];
    __shared__ float Bs[16][128 + 4];
    __shared__ float redV[128][17];
    __shared__ int   redI[128][17];

    const int tid = threadIdx.x;
    const int m0  = blockIdx.x * 128;   // t' base
    const int n0  = blockIdx.y * 128;   // bin base
    const int tx  = tid & 15;
    const int ty  = tid >> 4;

    float acc[8][8];
    #pragma unroll
    for (int i = 0; i < 8; ++i)
        #pragma unroll
        for (int j = 0; j < 8; ++j) acc[i][j] = 0.f;

    for (int kb = 0; kb < DM / 16; ++kb) {
        #pragma unroll
        for (int it = 0; it < 2; ++it) {
            int idx = tid + it * 256;
            int row = idx >> 2;
            int c4  = (idx & 3) * 4;
            const float4 a4 = *(const float4*)(
                g_X + (size_t)(m0 + row) * DM + kb * 16 + c4);
            As[c4 + 0][row] = a4.x;  As[c4 + 1][row] = a4.y;
            As[c4 + 2][row] = a4.z;  As[c4 + 3][row] = a4.w;
            const float4 b4 = *(const float4*)(
                cb + (size_t)(n0 + row) * DM + kb * 16 + c4);
            Bs[c4 + 0][row] = b4.x;  Bs[c4 + 1][row] = b4.y;
            Bs[c4 + 2][row] = b4.z;  Bs[c4 + 3][row] = b4.w;
        }
        __syncthreads();

        #pragma unroll
        for (int kk = 0; kk < 16; ++kk) {
            float a[8], b[8];
            #pragma unroll
            for (int i = 0; i < 8; ++i) a[i] = As[kk][ty * 8 + i];
            #pragma unroll
            for (int j = 0; j < 8; ++j) b[j] = Bs[kk][tx * 8 + j];
            #pragma unroll
            for (int i = 0; i < 8; ++i)
                #pragma unroll
                for (int j = 0; j < 8; ++j) acc[i][j] += a[i] * b[j];
        }
        __syncthreads();
    }

    // Per-thread argmin over its 8 bins (ascending j, strict < => lowest index)
    #pragma unroll
    for (int i = 0; i < 8; ++i) {
        float best = 3.4e38f;
        int   bi   = n0 + tx * 8;
        #pragma unroll
        for (int j = 0; j < 8; ++j) {
            int n   = n0 + tx * 8 + j;
            float d = __ldg(&g_cnorm[n]) - 2.f * acc[i][j];
            if (d < best) { best = d; bi = n; }
        }
        redV[ty * 8 + i][tx] = best;
        redI[ty * 8 + i][tx] = bi;
    }
    __syncthreads();

    // Row-wise reduce across the 16 tx lanes (ascending tx => lowest bin wins ties)
    if (tid < 128) {
        float best = redV[tid][0];
        int   bi   = redI[tid][0];
        #pragma unroll
        for (int t = 1; t < 16; ++t) {
            float v = redV[tid][t];
            if (v < best) { best = v; bi = redI[tid][t]; }
        }
        g_pmin[(size_t)(m0 + tid) * 8 + blockIdx.y] = best;
        g_pidx[(size_t)(m0 + tid) * 8 + blockIdx.y] = bi;
    }
}

// ---------------------------------------------------------------------------
// Kernel 3: final reduce over the 8 n-tiles per row (ascending => first-min).
// OUTPUT AS FLOAT: indices < 2^24 are exactly representable in fp32. The
// exactly-1.0 rel_err signature of the previous rounds matches int bit
// patterns (denormals ~= 0) being read as float32 by the harness.
// ---------------------------------------------------------------------------
__global__ void final_kernel(float* __restrict__ out) {
    int row = blockIdx.x * blockDim.x + threadIdx.x;
    if (row >= TQ) return;
    float best = g_pmin[(size_t)row * 8];
    int   bi   = g_pidx[(size_t)row * 8];
    #pragma unroll
    for (int t = 1; t < 8; ++t) {
        float v = g_pmin[(size_t)row * 8 + t];
        if (v < best) { best = v; bi = g_pidx[(size_t)row * 8 + t]; }
    }
    out[row] = (float)bi;
}

// ---------------------------------------------------------------------------
// Launch. Inputs are resolved BY ELEMENT COUNT (robust to metadata ordering):
//   ssl_content [8,768,16384] -> 100663296 elems (only batch 0 used)
//   conv_w      [768,768,2]   -> 1179648
//   conv_b      [768]         -> 768
//   codebook    [1024,768]    -> 786432
// (byte-count convention also accepted; all 8 values are pairwise distinct)
// Output: [1, 8192] argmin indices, written as float32.
// ---------------------------------------------------------------------------
static inline bool size_is(long long got, long long elems) {
    return got == elems || got == elems * 4;  // elements or bytes
}

extern "C" void kernel_launch(void* const* d_in, const int* in_sizes, int n_in,
                              void* d_out, int out_size) {
    const float* ssl  = nullptr;
    const float* W    = nullptr;
    const float* bias = nullptr;
    const float* cb   = nullptr;

    for (int i = 0; i < n_in; ++i) {
        long long s = (long long)in_sizes[i];
        if      (size_is(s, 8LL * 768 * 16384)) ssl  = (const float*)d_in[i];
        else if (size_is(s, 768LL * 768 * 2))   W    = (const float*)d_in[i];
        else if (size_is(s, 768LL))             bias = (const float*)d_in[i];
        else if (size_is(s, 1024LL * 768))      cb   = (const float*)d_in[i];
    }
    // Fallback to declaration order if anything unmatched
    if (!ssl || !W || !bias || !cb) {
        ssl  = (const float*)d_in[0];
        W    = (const float*)d_in[1];
        bias = (const float*)d_in[2];
        cb   = (const float*)d_in[3];
    }
    float* out = (float*)d_out;

    cnorm_kernel<<<128, 256>>>(cb);

    dim3 g1(TQ / 128, DM / 128);                 // 64 x 6
    conv_gemm_kernel<<<g1, 256>>>(ssl, W, bias);

    dim3 g2(TQ / 128, NBINS / 128);              // 64 x 8
    dist_kernel<<<g2, 256>>>(cb);

    final_kernel<<<TQ / 256, 256>>>(out);
}

// round 7
// speedup vs baseline: 1.0018x; 1.0018x over previous
#include <cuda_runtime.h>

// Problem constants
#define TQ     8192      // T/2 output positions
#define DM     768       // model dim
#define NBINS  1024      // codebook entries
#define TIN    16384     // input T
#define KCONV  1536      // conv GEMM K = D*2

typedef unsigned long long u64;

// Scratch (allocation-free rule: __device__ globals)
__device__ float g_X[TQ * DM];          // conv output, [t'][d] row-major (25 MB)
__device__ float g_cnorm[NBINS];        // ||c_k||^2
__device__ float g_pmin[TQ * 8];        // per-(row, n-tile) partial min
__device__ int   g_pidx[TQ * 8];        // per-(row, n-tile) partial argmin

// ---------------------------------------------------------------------------
// Packed f32x2 helpers (Blackwell FFMA2 path — 2x fp32 FMA throughput,
// bit-identical .rn rounding to scalar fmaf)
// ---------------------------------------------------------------------------
__device__ __forceinline__ u64 pack2(float x, float y) {
    u64 r;
    asm("mov.b64 %0, {%1, %2};" : "=l"(r) : "f"(x), "f"(y));
    return r;
}
__device__ __forceinline__ void fma2(u64& d, u64 a, u64 b) {
    asm("fma.rn.f32x2 %0, %1, %2, %3;" : "=l"(d) : "l"(a), "l"(b), "l"(d));
}
__device__ __forceinline__ float2 unpack2(u64 v) {
    float2 r;
    asm("mov.b64 {%0, %1}, %2;" : "=f"(r.x), "=f"(r.y) : "l"(v));
    return r;
}

// ---------------------------------------------------------------------------
// Kernel 0: codebook squared norms. One warp per codebook row.
// ---------------------------------------------------------------------------
__global__ void cnorm_kernel(const float* __restrict__ cb) {
    int warp = (blockIdx.x * blockDim.x + threadIdx.x) >> 5;
    int lane = threadIdx.x & 31;
    if (warp >= NBINS) return;
    const float* row = cb + warp * DM;
    float s = 0.f;
    for (int i = lane; i < DM; i += 32) { float v = row[i]; s += v * v; }
    #pragma unroll
    for (int o = 16; o; o >>= 1) s += __shfl_xor_sync(0xffffffffu, s, o);
    if (lane == 0) g_cnorm[warp] = s;
}

// ---------------------------------------------------------------------------
// Kernel 1: conv-as-GEMM.  X[t', d_out] = sum_dk A[t',dk] * W[d_out,dk] + b
//   A[t', 2*d_in+k] = ssl[d_in*TIN + 2*t' + k]   (batch 0 only)
//   W row-major [768][1536]  (conv_w [O][I][K] flattened, cross-correlation)
// BM=BN=128, BK=16, 256 threads, 8x8 microtile, FFMA2 mainloop.
// ---------------------------------------------------------------------------
__global__ __launch_bounds__(256, 2) void conv_gemm_kernel(
    const float* __restrict__ ssl,     // batch 0 base: [768][16384]
    const float* __restrict__ W,       // [768][1536]
    const float* __restrict__ bias)    // [768]
{
    __shared__ __align__(16) float As[16][128 + 4];  // [dk_local][m_local]
    __shared__ __align__(16) float Bs[16][128 + 4];  // [dk_local][n_local]

    const int tid = threadIdx.x;
    const int m0  = blockIdx.x * 128;  // t' base
    const int n0  = blockIdx.y * 128;  // d_out base
    const int tx  = tid & 15;
    const int ty  = tid >> 4;
    const int r   = tid & 127;         // A-load row (t' local)
    const int di0 = tid >> 7;          // A-load d_in phase (0..1)

    u64 acc[8][4];                     // [m_i][n_pair], packed along n
    #pragma unroll
    for (int i = 0; i < 8; ++i)
        #pragma unroll
        for (int j = 0; j < 4; ++j) acc[i][j] = 0ULL;

    for (int kb = 0; kb < KCONV / 16; ++kb) {
        // A tile: 8 d_in rows x 128 t' as contiguous float2 (both conv taps)
        #pragma unroll
        for (int l = 0; l < 4; ++l) {
            int di = di0 + l * 2;                           // 0..7
            const float2 v = *(const float2*)(
                ssl + (size_t)(kb * 8 + di) * TIN + 2 * (m0 + r));
            As[2 * di + 0][r] = v.x;                        // k = 0 tap
            As[2 * di + 1][r] = v.y;                        // k = 1 tap
        }
        // B tile: W[n0+row][kb*16 .. +16), stored transposed into Bs[dk][n]
        #pragma unroll
        for (int it = 0; it < 2; ++it) {
            int idx = tid + it * 256;
            int row = idx >> 2;
            int c4  = (idx & 3) * 4;
            const float4 w4 = *(const float4*)(
                W + (size_t)(n0 + row) * KCONV + kb * 16 + c4);
            Bs[c4 + 0][row] = w4.x;  Bs[c4 + 1][row] = w4.y;
            Bs[c4 + 2][row] = w4.z;  Bs[c4 + 3][row] = w4.w;
        }
        __syncthreads();

        #pragma unroll
        for (int kk = 0; kk < 16; ++kk) {
            // a: 8 floats (2x LDS.128, broadcast across tx), dup-packed
            const float4 av0 = *(const float4*)&As[kk][ty * 8 + 0];
            const float4 av1 = *(const float4*)&As[kk][ty * 8 + 4];
            u64 a2[8];
            a2[0] = pack2(av0.x, av0.x);  a2[1] = pack2(av0.y, av0.y);
            a2[2] = pack2(av0.z, av0.z);  a2[3] = pack2(av0.w, av0.w);
            a2[4] = pack2(av1.x, av1.x);  a2[5] = pack2(av1.y, av1.y);
            a2[6] = pack2(av1.z, av1.z);  a2[7] = pack2(av1.w, av1.w);
            // b: 8 floats = 4 packed pairs (2x LDS.128 reinterpret)
            const ulonglong2 bv0 = *(const ulonglong2*)&Bs[kk][tx * 8 + 0];
            const ulonglong2 bv1 = *(const ulonglong2*)&Bs[kk][tx * 8 + 4];
            u64 b2[4] = { bv0.x, bv0.y, bv1.x, bv1.y };
            #pragma unroll
            for (int i = 0; i < 8; ++i)
                #pragma unroll
                for (int j = 0; j < 4; ++j) fma2(acc[i][j], a2[i], b2[j]);
        }
        __syncthreads();
    }

    // Epilogue: add bias, store [t'][d] row-major
    #pragma unroll
    for (int i = 0; i < 8; ++i) {
        int m = m0 + ty * 8 + i;
        #pragma unroll
        for (int j = 0; j < 4; ++j) {
            int n = n0 + tx * 8 + 2 * j;
            float2 v = unpack2(acc[i][j]);
            g_X[(size_t)m * DM + n + 0] = v.x + __ldg(&bias[n + 0]);
            g_X[(size_t)m * DM + n + 1] = v.y + __ldg(&bias[n + 1]);
        }
    }
}

// ---------------------------------------------------------------------------
// Kernel 2: distance GEMM + per-tile argmin.
//   dot[t', n] = sum_k X[t',k] * cb[n,k];  d2 = cnorm[n] - 2*dot  (|x|^2 drops)
//   Each block: 128 rows x 128 bins, writes (min, argmin) partial per row.
// ---------------------------------------------------------------------------
__global__ __launch_bounds__(256, 2) void dist_kernel(const float* __restrict__ cb)
{
    __shared__ __align__(16) float As[16][128 + 4];
    __shared__ __align__(16) float Bs[16][128 + 4];
    __shared__ float redV[128][17];
    __shared__ int   redI[128][17];

    const int tid = threadIdx.x;
    const int m0  = blockIdx.x * 128;   // t' base
    const int n0  = blockIdx.y * 128;   // bin base
    const int tx  = tid & 15;
    const int ty  = tid >> 4;

    u64 acc[8][4];                      // [m_i][n_pair], packed along n
    #pragma unroll
    for (int i = 0; i < 8; ++i)
        #pragma unroll
        for (int j = 0; j < 4; ++j) acc[i][j] = 0ULL;

    for (int kb = 0; kb < DM / 16; ++kb) {
        #pragma unroll
        for (int it = 0; it < 2; ++it) {
            int idx = tid + it * 256;
            int row = idx >> 2;
            int c4  = (idx & 3) * 4;
            const float4 a4 = *(const float4*)(
                g_X + (size_t)(m0 + row) * DM + kb * 16 + c4);
            As[c4 + 0][row] = a4.x;  As[c4 + 1][row] = a4.y;
            As[c4 + 2][row] = a4.z;  As[c4 + 3][row] = a4.w;
            const float4 b4 = *(const float4*)(
                cb + (size_t)(n0 + row) * DM + kb * 16 + c4);
            Bs[c4 + 0][row] = b4.x;  Bs[c4 + 1][row] = b4.y;
            Bs[c4 + 2][row] = b4.z;  Bs[c4 + 3][row] = b4.w;
        }
        __syncthreads();

        #pragma unroll
        for (int kk = 0; kk < 16; ++kk) {
            const float4 av0 = *(const float4*)&As[kk][ty * 8 + 0];
            const float4 av1 = *(const float4*)&As[kk][ty * 8 + 4];
            u64 a2[8];
            a2[0] = pack2(av0.x, av0.x);  a2[1] = pack2(av0.y, av0.y);
            a2[2] = pack2(av0.z, av0.z);  a2[3] = pack2(av0.w, av0.w);
            a2[4] = pack2(av1.x, av1.x);  a2[5] = pack2(av1.y, av1.y);
            a2[6] = pack2(av1.z, av1.z);  a2[7] = pack2(av1.w, av1.w);
            const ulonglong2 bv0 = *(const ulonglong2*)&Bs[kk][tx * 8 + 0];
            const ulonglong2 bv1 = *(const ulonglong2*)&Bs[kk][tx * 8 + 4];
            u64 b2[4] = { bv0.x, bv0.y, bv1.x, bv1.y };
            #pragma unroll
            for (int i = 0; i < 8; ++i)
                #pragma unroll
                for (int j = 0; j < 4; ++j) fma2(acc[i][j], a2[i], b2[j]);
        }
        __syncthreads();
    }

    // Per-thread argmin over its 8 bins (ascending n, strict < => lowest index)
    #pragma unroll
    for (int i = 0; i < 8; ++i) {
        float best = 3.4e38f;
        int   bi   = n0 + tx * 8;
        #pragma unroll
        for (int j = 0; j < 4; ++j) {
            int n = n0 + tx * 8 + 2 * j;
            float2 v = unpack2(acc[i][j]);
            float d0 = __ldg(&g_cnorm[n + 0]) - 2.f * v.x;
            float d1 = __ldg(&g_cnorm[n + 1]) - 2.f * v.y;
            if (d0 < best) { best = d0; bi = n + 0; }
            if (d1 < best) { best = d1; bi = n + 1; }
        }
        redV[ty * 8 + i][tx] = best;
        redI[ty * 8 + i][tx] = bi;
    }
    __syncthreads();

    // Row-wise reduce across the 16 tx lanes (ascending tx => lowest bin wins ties)
    if (tid < 128) {
        float best = redV[tid][0];
        int   bi   = redI[tid][0];
        #pragma unroll
        for (int t = 1; t < 16; ++t) {
            float v = redV[tid][t];
            if (v < best) { best = v; bi = redI[tid][t]; }
        }
        g_pmin[(size_t)(m0 + tid) * 8 + blockIdx.y] = best;
        g_pidx[(size_t)(m0 + tid) * 8 + blockIdx.y] = bi;
    }
}

// ---------------------------------------------------------------------------
// Kernel 3: final reduce over the 8 n-tiles per row (ascending => first-min).
// Output written as float32 (harness output dtype); indices < 2^24 are exact.
// ---------------------------------------------------------------------------
__global__ void final_kernel(float* __restrict__ out) {
    int row = blockIdx.x * blockDim.x + threadIdx.x;
    if (row >= TQ) return;
    float best = g_pmin[(size_t)row * 8];
    int   bi   = g_pidx[(size_t)row * 8];
    #pragma unroll
    for (int t = 1; t < 8; ++t) {
        float v = g_pmin[(size_t)row * 8 + t];
        if (v < best) { best = v; bi = g_pidx[(size_t)row * 8 + t]; }
    }
    out[row] = (float)bi;
}

// ---------------------------------------------------------------------------
// Launch. Inputs are resolved BY ELEMENT COUNT (robust to metadata ordering):
//   ssl_content [8,768,16384] -> 100663296 elems (only batch 0 used)
//   conv_w      [768,768,2]   -> 1179648
//   conv_b      [768]         -> 768
//   codebook    [1024,768]    -> 786432
// Output: [1, 8192] argmin indices, written as float32.
// ---------------------------------------------------------------------------
static inline bool size_is(long long got, long long elems) {
    return got == elems || got == elems * 4;  // elements or bytes
}

extern "C" void kernel_launch(void* const* d_in, const int* in_sizes, int n_in,
                              void* d_out, int out_size) {
    const float* ssl  = nullptr;
    const float* W    = nullptr;
    const float* bias = nullptr;
    const float* cb   = nullptr;

    for (int i = 0; i < n_in; ++i) {
        long long s = (long long)in_sizes[i];
        if      (size_is(s, 8LL * 768 * 16384)) ssl  = (const float*)d_in[i];
        else if (size_is(s, 768LL * 768 * 2))   W    = (const float*)d_in[i];
        else if (size_is(s, 768LL))             bias = (const float*)d_in[i];
        else if (size_is(s, 1024LL * 768))      cb   = (const float*)d_in[i];
    }
    if (!ssl || !W || !bias || !cb) {
        ssl  = (const float*)d_in[0];
        W    = (const float*)d_in[1];
        bias = (const float*)d_in[2];
        cb   = (const float*)d_in[3];
    }
    float* out = (float*)d_out;

    cnorm_kernel<<<128, 256>>>(cb);

    dim3 g1(TQ / 128, DM / 128);                 // 64 x 6
    conv_gemm_kernel<<<g1, 256>>>(ssl, W, bias);

    dim3 g2(TQ / 128, NBINS / 128);              // 64 x 8
    dist_kernel<<<g2, 256>>>(cb);

    final_kernel<<<TQ / 256, 256>>>(out);
}